// round 12
// baseline (speedup 1.0000x reference)
#include <cuda_runtime.h>

#define N_BATCH 4
#define C_TOTAL 2048
#define T_FR    8
#define HH      16
#define WW      16
#define R_ROIS  32
#define OUT_SZ  16
#define SCALE   (1.0f/16.0f)

#define C_PER    8
#define HALF     4
#define C_CHUNKS (C_TOTAL / C_PER)       // 256

#define PSTR     17                       // plane row stride in float4 units
#define PLANE_SM (HH * PSTR)              // 272 float4 per half-plane-set

#define OUT_ELEMS   (R_ROIS * C_TOTAL * OUT_SZ * OUT_SZ)   // 16777216
#define FEATP_ELEMS (N_BATCH * C_TOTAL * HH * WW)          // 2097152

// 3-tap merged weights for one axis / output coordinate u; the three clamped
// cell offsets (scaled by mulstep) packed 8-bit each into .w.
// ratio=2: two samples' floors differ by <=1 -> 4 bilinear taps fit in 3
// consecutive cells; clamped duplicates just sum weights. w2==0 iff the two
// samples share a cell (common), enabling warp-uniform tap-3 skips.
__device__ __forceinline__ float4 axis_taps3(float lo, float binsz, int u,
                                             int mulstep) {
    float g0  = ((float)(2 * u) + 0.5f) * 0.5f;
    float s0  = lo + g0 * binsz;
    float s1  = s0 + 0.5f * binsz;
    float vm0 = (s0 >= -1.0f && s0 <= 16.0f) ? 0.5f : 0.0f;
    float vm1 = (s1 >= -1.0f && s1 <= 16.0f) ? 0.5f : 0.0f;
    float x0  = fminf(fmaxf(s0, 0.0f), 15.0f);
    float x1  = fminf(fmaxf(s1, 0.0f), 15.0f);
    float f0  = floorf(x0);
    float f1  = floorf(x1);
    float l0  = x0 - f0;
    float l1  = x1 - f1;
    bool  same = (f1 == f0);
    float4 rec;
    rec.x = (1.0f - l0) * vm0 + (same ? (1.0f - l1) * vm1 : 0.0f);
    rec.y = l0 * vm0 + (same ? l1 * vm1 : (1.0f - l1) * vm1);
    rec.z = same ? 0.0f : l1 * vm1;
    int b  = (int)f0;
    int o0 = b * mulstep;
    int o1 = min(b + 1, 15) * mulstep;
    int o2 = min(b + 2, 15) * mulstep;
    rec.w = __int_as_float(o0 | (o1 << 8) | (o2 << 16));
    return rec;
}

// RoI pass over one half's 4 channels (float4-interleaved planes).
__device__ __forceinline__ void roi_pass(
        const float4* __restrict__ pl,
        const float4* __restrict__ s_xtap,
        const float4* __restrict__ s_ytap,
        const int* __restrict__ s_list, int nr,
        int lx, int ly, int hi,
        float* __restrict__ outb, int tid) {
    for (int i = 0; i < nr; i++) {
        const int r = s_list[i];
        const float4 vx = s_xtap[r * 16 + lx];
        const float4 vy = s_ytap[r * 16 + ly];
        const int pk  = __float_as_int(vy.w);
        const int xk  = __float_as_int(vx.w);
        const int YR0 = (pk & 255) + lx;
        const int YR1 = ((pk >> 8) & 255) + lx;
        const int S0  = hi | (xk & 255);
        const int S1  = hi | ((xk >> 8) & 255);

        const float4 t0 = pl[YR0];
        const float4 t1 = pl[YR1];
        float4 a;
        a.x = fmaf(vy.y, t1.x, vy.x * t0.x);
        a.y = fmaf(vy.y, t1.y, vy.x * t0.y);
        a.z = fmaf(vy.y, t1.z, vy.x * t0.z);
        a.w = fmaf(vy.y, t1.w, vy.x * t0.w);
        if (__ballot_sync(0xffffffffu, vy.z != 0.0f)) {   // warp-uniform
            const int YR2 = ((pk >> 16) & 255) + lx;
            const float4 t2 = pl[YR2];
            a.x = fmaf(vy.z, t2.x, a.x);
            a.y = fmaf(vy.z, t2.y, a.y);
            a.z = fmaf(vy.z, t2.z, a.z);
            a.w = fmaf(vy.z, t2.w, a.w);
        }

        float v0 =      vx.x * __shfl_sync(0xffffffffu, a.x, S0);
        v0 = fmaf(vx.y, __shfl_sync(0xffffffffu, a.x, S1), v0);
        float v1 =      vx.x * __shfl_sync(0xffffffffu, a.y, S0);
        v1 = fmaf(vx.y, __shfl_sync(0xffffffffu, a.y, S1), v1);
        float v2 =      vx.x * __shfl_sync(0xffffffffu, a.z, S0);
        v2 = fmaf(vx.y, __shfl_sync(0xffffffffu, a.z, S1), v2);
        float v3 =      vx.x * __shfl_sync(0xffffffffu, a.w, S0);
        v3 = fmaf(vx.y, __shfl_sync(0xffffffffu, a.w, S1), v3);
        if (__ballot_sync(0xffffffffu, vx.z != 0.0f)) {   // warp-uniform
            const int S2 = hi | ((xk >> 16) & 255);
            v0 = fmaf(vx.z, __shfl_sync(0xffffffffu, a.x, S2), v0);
            v1 = fmaf(vx.z, __shfl_sync(0xffffffffu, a.y, S2), v1);
            v2 = fmaf(vx.z, __shfl_sync(0xffffffffu, a.z, S2), v2);
            v3 = fmaf(vx.z, __shfl_sync(0xffffffffu, a.w, S2), v3);
        }

        float* op = outb + r * (C_TOTAL * HH * WW) + tid;
        __stcs(op,                    v0);
        __stcs(op + 1 * (HH * WW),    v1);
        __stcs(op + 2 * (HH * WW),    v2);
        __stcs(op + 3 * (HH * WW),    v3);
    }
}

// ---------------------------------------------------------------------------
// Single fused, software-pipelined kernel (int32 indexing).
// Block = (8-channel chunk, batch nb), 256 threads; chunk split in 2 halves.
// Planes float4-interleaved (4 channels/pixel) -> y-pass is 2-3 LDS.128/roi.
//   LDG(h0) -> taps+ballot -> reduce h0 -> LDG(h1) -> STS h0 -> sync
//   -> roi(h0) [h1 in flight] -> reduce h1 -> STS h1 -> sync -> roi(h1)
// ---------------------------------------------------------------------------
__global__ __launch_bounds__(256, 5) void fused_kernel(
        const float* __restrict__ feat,
        const float* __restrict__ rois,
        float* __restrict__ out,
        float* __restrict__ featp) {
    const int nb    = blockIdx.y;
    const int cbase = blockIdx.x * C_PER;
    const int tid   = threadIdx.x;

    __shared__ float4 s_xtap[R_ROIS * 16];              // 8 KB
    __shared__ float4 s_ytap[R_ROIS * 16];              // 8 KB
    __shared__ float4 planes[2][PLANE_SM];              // 8.7 KB
    __shared__ int    s_list[R_ROIS];
    __shared__ int    s_cnt;

    // load mapping: one channel (of 4 per half) x one float4 pixel group
    const int c    = tid >> 6;          // 0..3
    const int q    = tid & 63;
    const int ppy  = q >> 2;            // plane row
    const int ppx  = (q & 3) * 4;       // first pixel in row
    const int nc0  = nb * C_TOTAL + cbase + c;
    const float4* src0 = (const float4*)feat + nc0 * (T_FR * 64) + q;

    // ---- issue half-0 loads ----
    float4 L[T_FR];
    #pragma unroll
    for (int t = 0; t < T_FR; t++) L[t] = __ldg(src0 + t * 64);

    // ---- tap table + roi list (overlaps h0 load latency) ----
    #pragma unroll
    for (int k = tid; k < R_ROIS * 16; k += 256) {
        const int r = k >> 4, u = k & 15;
        const float bx1 = rois[r * 5 + 1] * SCALE - 0.5f;
        const float by1 = rois[r * 5 + 2] * SCALE - 0.5f;
        const float bx2 = rois[r * 5 + 3] * SCALE - 0.5f;
        const float by2 = rois[r * 5 + 4] * SCALE - 0.5f;
        s_xtap[k] = axis_taps3(bx1, (bx2 - bx1) * (1.0f / OUT_SZ), u, 1);
        s_ytap[k] = axis_taps3(by1, (by2 - by1) * (1.0f / OUT_SZ), u, PSTR);
    }
    if (tid < 32) {
        int match = ((int)rois[tid * 5 + 0] == nb);
        unsigned m = __ballot_sync(0xffffffffu, match);
        if (match) s_list[__popc(m & ((1u << tid) - 1u))] = tid;
        if (tid == 0) s_cnt = __popc(m);
    }

    // component-c slot at 4 consecutive pixels (float4-interleaved planes)
    float* sp0 = (float*)&planes[0][ppy * PSTR + ppx] + c;
    float* sp1 = (float*)&planes[1][ppy * PSTR + ppx] + c;

    // ---- reduce half 0, write featp, start half-1 loads, stage smem ----
    float4 a = L[0];
    #pragma unroll
    for (int t = 1; t < T_FR; t++) {
        a.x += L[t].x; a.y += L[t].y; a.z += L[t].z; a.w += L[t].w;
    }
    a.x *= 0.125f; a.y *= 0.125f; a.z *= 0.125f; a.w *= 0.125f;
    __stcs((float4*)featp + nc0 * 64 + q, a);

    const float4* src1 = src0 + HALF * (T_FR * 64);
    #pragma unroll
    for (int t = 0; t < T_FR; t++) L[t] = __ldg(src1 + t * 64);

    sp0[0] = a.x; sp0[4] = a.y; sp0[8] = a.z; sp0[12] = a.w;
    __syncthreads();

    // ---- roi compute, half 0 (h1 loads in flight) ----
    const int lx = tid & 15;
    const int ly = tid >> 4;
    const int hi = tid & 16;
    const int nr = s_cnt;

    roi_pass(planes[0], s_xtap, s_ytap, s_list, nr, lx, ly, hi,
             out + cbase * (HH * WW), tid);

    // ---- reduce half 1, stage smem ----
    float4 b = L[0];
    #pragma unroll
    for (int t = 1; t < T_FR; t++) {
        b.x += L[t].x; b.y += L[t].y; b.z += L[t].z; b.w += L[t].w;
    }
    b.x *= 0.125f; b.y *= 0.125f; b.z *= 0.125f; b.w *= 0.125f;
    __stcs((float4*)featp + (nc0 + HALF) * 64 + q, b);
    sp1[0] = b.x; sp1[4] = b.y; sp1[8] = b.z; sp1[12] = b.w;
    __syncthreads();

    // ---- roi compute, half 1 ----
    roi_pass(planes[1], s_xtap, s_ytap, s_list, nr, lx, ly, hi,
             out + (cbase + HALF) * (HH * WW), tid);
}

// ---------------------------------------------------------------------------
extern "C" void kernel_launch(void* const* d_in, const int* in_sizes, int n_in,
                              void* d_out, int out_size) {
    const float* feat = (const float*)d_in[0];
    const float* rois = (const float*)d_in[1];
    float* out   = (float*)d_out;
    float* featp = out + OUT_ELEMS;   // feat_p is the 2nd tuple element

    dim3 grid(C_CHUNKS, N_BATCH);     // 256 x 4 = 1024 blocks
    fused_kernel<<<grid, 256>>>(feat, rois, out, featp);
}

// round 13
// speedup vs baseline: 1.0583x; 1.0583x over previous
#include <cuda_runtime.h>

#define N_BATCH 4
#define C_TOTAL 2048
#define T_FR    8
#define HH      16
#define WW      16
#define R_ROIS  32
#define OUT_SZ  16
#define SCALE   (1.0f/16.0f)

#define C_PER    8
#define NPAIR    (C_PER / 2)              // 4 float2 plane-pairs
#define C_CHUNKS (C_TOTAL / C_PER)        // 256

#define PSTR     17                        // plane row stride (float2 units)
#define PLANE_SM (HH * PSTR)               // 272 float2 per pair-plane

#define OUT_ELEMS   (R_ROIS * C_TOTAL * OUT_SZ * OUT_SZ)   // 16777216
#define FEATP_ELEMS (N_BATCH * C_TOTAL * HH * WW)          // 2097152

// 3-tap merged weights for one axis / output coordinate u; the three clamped
// cell offsets (scaled by mulstep) packed 8-bit each into .w.
// ratio=2: two samples' floors differ by <=1 -> 4 bilinear taps fit in 3
// consecutive cells {b, b+1, b+2}; clamped duplicates just sum weights.
__device__ __forceinline__ float4 axis_taps3(float lo, float binsz, int u,
                                             int mulstep) {
    float g0  = ((float)(2 * u) + 0.5f) * 0.5f;
    float s0  = lo + g0 * binsz;
    float s1  = s0 + 0.5f * binsz;
    float vm0 = (s0 >= -1.0f && s0 <= 16.0f) ? 0.5f : 0.0f;
    float vm1 = (s1 >= -1.0f && s1 <= 16.0f) ? 0.5f : 0.0f;
    float x0  = fminf(fmaxf(s0, 0.0f), 15.0f);
    float x1  = fminf(fmaxf(s1, 0.0f), 15.0f);
    float f0  = floorf(x0);
    float f1  = floorf(x1);
    float l0  = x0 - f0;
    float l1  = x1 - f1;
    bool  same = (f1 == f0);
    float4 rec;
    rec.x = (1.0f - l0) * vm0 + (same ? (1.0f - l1) * vm1 : 0.0f);
    rec.y = l0 * vm0 + (same ? l1 * vm1 : (1.0f - l1) * vm1);
    rec.z = same ? 0.0f : l1 * vm1;
    int b  = (int)f0;
    int o0 = b * mulstep;
    int o1 = min(b + 1, 15) * mulstep;
    int o2 = min(b + 2, 15) * mulstep;
    rec.w = __int_as_float(o0 | (o1 << 8) | (o2 << 16));
    return rec;
}

// ---------------------------------------------------------------------------
// Single fused kernel, ONE-WAVE sizing: 1024 blocks, 7 blocks/SM (36 regs).
// Block = (8-channel chunk, batch nb), 256 threads.
// Phase 0/1: taps+ballot overlapped with MLP-4 temporal-mean loads; planes
//            stored channel-pair interleaved (float2, pad 17). One sync.
// Phase 2:   per matched roi: 3-tap y-pass (LDS.64 pairs), 3-shuffle x-pass,
//            streaming stores. Latency hidden by ~56 warps/SM occupancy.
// ---------------------------------------------------------------------------
__global__ __launch_bounds__(256, 7) void fused_kernel(
        const float* __restrict__ feat,
        const float* __restrict__ rois,
        float* __restrict__ out,
        float* __restrict__ featp) {
    const int nb    = blockIdx.y;
    const int cbase = blockIdx.x * C_PER;
    const int tid   = threadIdx.x;

    __shared__ float4 s_xtap[R_ROIS * 16];              // 8 KB
    __shared__ float4 s_ytap[R_ROIS * 16];              // 8 KB
    __shared__ float2 planes[NPAIR * PLANE_SM];         // 8.7 KB
    __shared__ int    s_list[R_ROIS];
    __shared__ int    s_cnt;

    // load mapping: channels c and c+4, one float4 pixel group each
    const int c    = tid >> 6;          // 0..3
    const int q    = tid & 63;
    const int ppy  = q >> 2;            // plane row
    const int ppx  = (q & 3) * 4;       // first pixel in row
    const int nc0  = nb * C_TOTAL + cbase + c;
    const float4* src0 = (const float4*)feat + nc0 * (T_FR * 64) + q;

    // ---- issue first MLP-4 batch for channel c ----
    float4 p0 = __ldg(src0);
    float4 p1 = __ldg(src0 + 64);
    float4 p2 = __ldg(src0 + 128);
    float4 p3 = __ldg(src0 + 192);

    // ---- tap table + roi list (overlaps load latency) ----
    #pragma unroll
    for (int k = tid; k < R_ROIS * 16; k += 256) {
        const int r = k >> 4, u = k & 15;
        const float bx1 = rois[r * 5 + 1] * SCALE - 0.5f;
        const float by1 = rois[r * 5 + 2] * SCALE - 0.5f;
        const float bx2 = rois[r * 5 + 3] * SCALE - 0.5f;
        const float by2 = rois[r * 5 + 4] * SCALE - 0.5f;
        s_xtap[k] = axis_taps3(bx1, (bx2 - bx1) * (1.0f / OUT_SZ), u, 1);
        s_ytap[k] = axis_taps3(by1, (by2 - by1) * (1.0f / OUT_SZ), u, PSTR);
    }
    if (tid < 32) {
        int match = ((int)rois[tid * 5 + 0] == nb);
        unsigned m = __ballot_sync(0xffffffffu, match);
        if (match) s_list[__popc(m & ((1u << tid) - 1u))] = tid;
        if (tid == 0) s_cnt = __popc(m);
    }

    // ---- finish channel c, then channel c+4 (MLP-4 each) ----
    {
        float4 a;
        a.x = (p0.x + p1.x) + (p2.x + p3.x);
        a.y = (p0.y + p1.y) + (p2.y + p3.y);
        a.z = (p0.z + p1.z) + (p2.z + p3.z);
        a.w = (p0.w + p1.w) + (p2.w + p3.w);
        p0 = __ldg(src0 + 256); p1 = __ldg(src0 + 320);
        p2 = __ldg(src0 + 384); p3 = __ldg(src0 + 448);
        a.x += (p0.x + p1.x) + (p2.x + p3.x);
        a.y += (p0.y + p1.y) + (p2.y + p3.y);
        a.z += (p0.z + p1.z) + (p2.z + p3.z);
        a.w += (p0.w + p1.w) + (p2.w + p3.w);
        a.x *= 0.125f; a.y *= 0.125f; a.z *= 0.125f; a.w *= 0.125f;
        __stcs((float4*)featp + nc0 * 64 + q, a);
        float* sp = (float*)&planes[(c >> 1) * PLANE_SM + ppy * PSTR]
                  + ppx * 2 + (c & 1);
        sp[0] = a.x; sp[2] = a.y; sp[4] = a.z; sp[6] = a.w;
    }
    {
        const float4* src1 = src0 + 4 * (T_FR * 64);
        p0 = __ldg(src1);       p1 = __ldg(src1 + 64);
        p2 = __ldg(src1 + 128); p3 = __ldg(src1 + 192);
        float4 a;
        a.x = (p0.x + p1.x) + (p2.x + p3.x);
        a.y = (p0.y + p1.y) + (p2.y + p3.y);
        a.z = (p0.z + p1.z) + (p2.z + p3.z);
        a.w = (p0.w + p1.w) + (p2.w + p3.w);
        p0 = __ldg(src1 + 256); p1 = __ldg(src1 + 320);
        p2 = __ldg(src1 + 384); p3 = __ldg(src1 + 448);
        a.x += (p0.x + p1.x) + (p2.x + p3.x);
        a.y += (p0.y + p1.y) + (p2.y + p3.y);
        a.z += (p0.z + p1.z) + (p2.z + p3.z);
        a.w += (p0.w + p1.w) + (p2.w + p3.w);
        a.x *= 0.125f; a.y *= 0.125f; a.z *= 0.125f; a.w *= 0.125f;
        const int cc = c + 4;
        __stcs((float4*)featp + (nc0 + 4) * 64 + q, a);
        float* sp = (float*)&planes[(cc >> 1) * PLANE_SM + ppy * PSTR]
                  + ppx * 2 + (cc & 1);
        sp[0] = a.x; sp[2] = a.y; sp[4] = a.z; sp[6] = a.w;
    }
    __syncthreads();

    // ---------------- Phase 2: RoIAlign over matched rois ----------------
    const int lx = tid & 15;
    const int ly = tid >> 4;
    const int hi = tid & 16;
    const int nr = s_cnt;

    for (int i = 0; i < nr; i++) {
        const int r = s_list[i];
        const float4 vx = s_xtap[r * 16 + lx];
        const float4 vy = s_ytap[r * 16 + ly];
        const int pk  = __float_as_int(vy.w);
        const int YR0 = (pk & 255) + lx;
        const int YR1 = ((pk >> 8) & 255) + lx;
        const int YR2 = ((pk >> 16) & 255) + lx;
        const int xk  = __float_as_int(vx.w);
        const int S0  = hi | (xk & 255);
        const int S1  = hi | ((xk >> 8) & 255);
        const int S2  = hi | ((xk >> 16) & 255);
        float* opb = out + (r * C_TOTAL + cbase) * (HH * WW) + tid;
        #pragma unroll
        for (int p = 0; p < NPAIR; p++) {
            const float2* pl = &planes[p * PLANE_SM];
            const float2 t0 = pl[YR0], t1 = pl[YR1], t2 = pl[YR2];
            float ta = fmaf(vy.z, t2.x, fmaf(vy.y, t1.x, vy.x * t0.x));
            float tb = fmaf(vy.z, t2.y, fmaf(vy.y, t1.y, vy.x * t0.y));
            float va =      vx.x * __shfl_sync(0xffffffffu, ta, S0);
            va = fmaf(vx.y, __shfl_sync(0xffffffffu, ta, S1), va);
            va = fmaf(vx.z, __shfl_sync(0xffffffffu, ta, S2), va);
            float vb =      vx.x * __shfl_sync(0xffffffffu, tb, S0);
            vb = fmaf(vx.y, __shfl_sync(0xffffffffu, tb, S1), vb);
            vb = fmaf(vx.z, __shfl_sync(0xffffffffu, tb, S2), vb);
            __stcs(opb + (2 * p)     * (HH * WW), va);
            __stcs(opb + (2 * p + 1) * (HH * WW), vb);
        }
    }
}

// ---------------------------------------------------------------------------
extern "C" void kernel_launch(void* const* d_in, const int* in_sizes, int n_in,
                              void* d_out, int out_size) {
    const float* feat = (const float*)d_in[0];
    const float* rois = (const float*)d_in[1];
    float* out   = (float*)d_out;
    float* featp = out + OUT_ELEMS;   // feat_p is the 2nd tuple element

    dim3 grid(C_CHUNKS, N_BATCH);     // 256 x 4 = 1024 blocks (one wave @7/SM)
    fused_kernel<<<grid, 256>>>(feat, rois, out, featp);
}